// round 2
// baseline (speedup 1.0000x reference)
#include <cuda_runtime.h>

#define SQ 1024   // sequence length (32*32)
#define CC 256    // QDIM == KDIM
#define EE 512    // EMBED
#define BB 8      // batch
#define HH 8      // heads
#define DD 64     // head dim

typedef unsigned long long u64;

// Scratch: Q/K/V in per-batch (E, S) layout.
__device__ float g_Q[BB * EE * SQ];
__device__ float g_K[BB * EE * SQ];
__device__ float g_V[BB * EE * SQ];

// ---- packed fp32x2 helpers (sm_103a) --------------------------------------
__device__ __forceinline__ u64 pk2(float lo, float hi) {
    u64 r; asm("mov.b64 %0,{%1,%2};" : "=l"(r) : "f"(lo), "f"(hi)); return r;
}
__device__ __forceinline__ void upk2(u64 v, float& lo, float& hi) {
    asm("mov.b64 {%0,%1},%2;" : "=f"(lo), "=f"(hi) : "l"(v));
}
__device__ __forceinline__ void fma2(u64& d, u64 a, u64 b) {
    asm("fma.rn.f32x2 %0,%1,%2,%0;" : "+l"(d) : "l"(a), "l"(b));
}
__device__ __forceinline__ void mul2(u64& d, u64 a) {
    asm("mul.rn.f32x2 %0,%0,%1;" : "+l"(d) : "l"(a));
}
__device__ __forceinline__ void add2(u64& d, u64 a) {
    asm("add.rn.f32x2 %0,%0,%1;" : "+l"(d) : "l"(a));
}
__device__ __forceinline__ float ex2f(float x) {
    float r; asm("ex2.approx.ftz.f32 %0,%1;" : "=f"(r) : "f"(x)); return r;
}

// ---------------------------------------------------------------------------
// Projection GEMM: Y[e][s] = sum_c W[e][c] * X[c][s] + bias[e]
// 128x128 tile, BK=16, 256 threads, 8x8 micro with f32x2 FMAs.
// ---------------------------------------------------------------------------
__global__ __launch_bounds__(256) void proj_kernel(
    const float* __restrict__ q_in, const float* __restrict__ k_in,
    const float* __restrict__ wq, const float* __restrict__ biasq,
    const float* __restrict__ wk, const float* __restrict__ biask,
    const float* __restrict__ wv, const float* __restrict__ biasv)
{
    const int z = blockIdx.z;
    const int b = z / 3;
    const int p = z % 3;
    const float* X    = (p == 0 ? q_in : k_in) + (size_t)b * CC * SQ;
    const float* W    = (p == 0) ? wq : (p == 1 ? wk : wv);
    const float* bias = (p == 0) ? biasq : (p == 1 ? biask : biasv);
    float* Y = (p == 0 ? g_Q : (p == 1 ? g_K : g_V)) + (size_t)b * EE * SQ;

    const int m0 = blockIdx.y * 128;
    const int n0 = blockIdx.x * 128;

    __shared__ __align__(16) float As[16][132];
    __shared__ __align__(16) float Bs[16][128];

    const int tid = threadIdx.x;
    const int tm = (tid / 16) * 8;
    const int tn = (tid % 16) * 8;

    u64 acc2[8][4];
    #pragma unroll
    for (int i = 0; i < 8; i++)
        #pragma unroll
        for (int j = 0; j < 4; j++) acc2[i][j] = 0ULL;

    for (int k0 = 0; k0 < CC; k0 += 16) {
        #pragma unroll
        for (int r = 0; r < 2; r++) {
            int t = tid + r * 256;
            int m  = t >> 2;
            int kq = (t & 3) * 4;
            float4 a = *(const float4*)(W + (size_t)(m0 + m) * CC + k0 + kq);
            As[kq + 0][m] = a.x;
            As[kq + 1][m] = a.y;
            As[kq + 2][m] = a.z;
            As[kq + 3][m] = a.w;
            int kb = t >> 5;
            int nq = (t & 31) * 4;
            *(float4*)(&Bs[kb][nq]) =
                *(const float4*)(X + (size_t)(k0 + kb) * SQ + n0 + nq);
        }
        __syncthreads();

        #pragma unroll
        for (int k = 0; k < 16; k++) {
            float a[8];
            *(float4*)&a[0] = *(const float4*)&As[k][tm];
            *(float4*)&a[4] = *(const float4*)&As[k][tm + 4];
            float4 b0 = *(const float4*)&Bs[k][tn];
            float4 b1 = *(const float4*)&Bs[k][tn + 4];
            u64 b2[4] = {pk2(b0.x, b0.y), pk2(b0.z, b0.w),
                         pk2(b1.x, b1.y), pk2(b1.z, b1.w)};
            #pragma unroll
            for (int i = 0; i < 8; i++) {
                u64 a2 = pk2(a[i], a[i]);
                fma2(acc2[i][0], a2, b2[0]);
                fma2(acc2[i][1], a2, b2[1]);
                fma2(acc2[i][2], a2, b2[2]);
                fma2(acc2[i][3], a2, b2[3]);
            }
        }
        __syncthreads();
    }

    #pragma unroll
    for (int i = 0; i < 8; i++) {
        float bv2 = __ldg(bias + m0 + tm + i);
        float o[8];
        upk2(acc2[i][0], o[0], o[1]);
        upk2(acc2[i][1], o[2], o[3]);
        upk2(acc2[i][2], o[4], o[5]);
        upk2(acc2[i][3], o[6], o[7]);
        float* yrow = Y + (size_t)(m0 + tm + i) * SQ + n0 + tn;
        float4 o0 = make_float4(o[0]+bv2, o[1]+bv2, o[2]+bv2, o[3]+bv2);
        float4 o1 = make_float4(o[4]+bv2, o[5]+bv2, o[6]+bv2, o[7]+bv2);
        *(float4*)yrow       = o0;
        *(float4*)(yrow + 4) = o1;
    }
}

// ---------------------------------------------------------------------------
// Causal flash attention, Br=Bc=128, f32x2 math.
// 256 threads. QK: 16(i)x16(j) threads, 8x8 micro. AV: two 128-thread groups
// each handle one j-half with 8(i)x8(d) micro; partials combined at the end.
// Dynamic smem 160KB: Qs[64][128] Ks[64][128] Vt[128][64] Ps[128][128].
// Vt chunk-swizzled: physical chunk pc = (c + (j>>2)) & 15.
// ---------------------------------------------------------------------------
__global__ __launch_bounds__(256, 1) void attn_kernel(float* __restrict__ out)
{
    extern __shared__ float smf[];
    float* Qs = smf;                  // [64][128]
    float* Ks = Qs + 64 * 128;        // [64][128]
    float* Vt = Ks + 64 * 128;        // [128][64] swizzled
    float* Ps = Vt + 128 * 64;        // [128][128]
    __shared__ float Corr[128];
    __shared__ float Lrow[128];

    const int qb = (int)(gridDim.x - 1 - blockIdx.x);  // heavy blocks first
    const int h  = blockIdx.y;
    const int b  = blockIdx.z;

    const float* Qh = g_Q + ((size_t)b * EE + h * DD) * SQ;
    const float* Kh = g_K + ((size_t)b * EE + h * DD) * SQ;
    const float* Vh = g_V + ((size_t)b * EE + h * DD) * SQ;
    float*       Oh = out + ((size_t)b * EE + h * DD) * SQ;

    const int tid = threadIdx.x;
    // QK map
    const int ti = tid >> 4, tj = tid & 15;
    const int i0 = ti * 8, j0 = tj * 8;
    // AV map
    const int gt   = tid & 127;
    const int grp  = tid >> 7;             // 0: j 0..63, 1: j 64..127
    const int ai0  = (gt >> 3) * 8;        // AV rows
    const int ad0  = (gt & 7) * 8;         // AV head-dim cols
    const int jbase = grp * 64;
    const int s0 = qb * 128;

    const float qscale = 0.125f * 1.4426950408889634f;  // 1/sqrt(64) * log2(e)

    // ---- load Q (scaled)
    for (int t = tid; t < 64 * 32; t += 256) {
        int d = t >> 5, ic = (t & 31) * 4;
        float4 q = *(const float4*)(Qh + (size_t)d * SQ + s0 + ic);
        q.x *= qscale; q.y *= qscale; q.z *= qscale; q.w *= qscale;
        *(float4*)(Qs + d * 128 + ic) = q;
    }

    float m_i[8], l_i[8];
    u64 o2[8][4];
    #pragma unroll
    for (int ii = 0; ii < 8; ii++) {
        m_i[ii] = -1e30f; l_i[ii] = 0.0f;
        #pragma unroll
        for (int dc = 0; dc < 4; dc++) o2[ii][dc] = 0ULL;
    }

    for (int kb = 0; kb <= qb; kb++) {
        __syncthreads();   // prev AV reads / Qs writes complete
        const int c0 = kb * 128;

        // ---- load K tile [d][j]
        for (int t = tid; t < 64 * 32; t += 256) {
            int d = t >> 5, jc = (t & 31) * 4;
            *(float4*)(Ks + d * 128 + jc) =
                *(const float4*)(Kh + (size_t)d * SQ + c0 + jc);
        }
        // ---- load V transposed to [j][d], 4x4 register transpose, swizzled
        for (int t = tid; t < 512; t += 256) {
            int dt = t >> 5, jt = t & 31;
            int d4 = dt * 4, j4 = jt * 4;
            const float* vp = Vh + (size_t)d4 * SQ + c0 + j4;
            float4 r0 = *(const float4*)(vp);
            float4 r1 = *(const float4*)(vp + SQ);
            float4 r2 = *(const float4*)(vp + 2 * SQ);
            float4 r3 = *(const float4*)(vp + 3 * SQ);
            int pc = (dt + jt) & 15;
            *(float4*)(Vt + (j4 + 0) * 64 + pc * 4) = make_float4(r0.x, r1.x, r2.x, r3.x);
            *(float4*)(Vt + (j4 + 1) * 64 + pc * 4) = make_float4(r0.y, r1.y, r2.y, r3.y);
            *(float4*)(Vt + (j4 + 2) * 64 + pc * 4) = make_float4(r0.z, r1.z, r2.z, r3.z);
            *(float4*)(Vt + (j4 + 3) * 64 + pc * 4) = make_float4(r0.w, r1.w, r2.w, r3.w);
        }
        __syncthreads();

        // ---- QK^T: 8x8 scores per thread, f32x2
        u64 s2[8][4];
        #pragma unroll
        for (int ii = 0; ii < 8; ii++)
            #pragma unroll
            for (int jc = 0; jc < 4; jc++) s2[ii][jc] = 0ULL;

        #pragma unroll 8
        for (int d = 0; d < 64; d++) {
            const float* qrow = Qs + d * 128;
            const float* krow = Ks + d * 128;
            float4 qa = *(const float4*)(qrow + i0);
            float4 qb4 = *(const float4*)(qrow + i0 + 4);
            float4 ka = *(const float4*)(krow + j0);
            float4 kb4 = *(const float4*)(krow + j0 + 4);
            u64 k2[4] = {pk2(ka.x, ka.y), pk2(ka.z, ka.w),
                         pk2(kb4.x, kb4.y), pk2(kb4.z, kb4.w)};
            float qv[8] = {qa.x, qa.y, qa.z, qa.w, qb4.x, qb4.y, qb4.z, qb4.w};
            #pragma unroll
            for (int ii = 0; ii < 8; ii++) {
                u64 a2 = pk2(qv[ii], qv[ii]);
                fma2(s2[ii][0], a2, k2[0]);
                fma2(s2[ii][1], a2, k2[1]);
                fma2(s2[ii][2], a2, k2[2]);
                fma2(s2[ii][3], a2, k2[3]);
            }
        }

        // ---- per-row softmax (row-wise across 16 tj lanes), write P
        const bool diag = (kb == qb);
        #pragma unroll
        for (int ii = 0; ii < 8; ii++) {
            float r[8];
            upk2(s2[ii][0], r[0], r[1]);
            upk2(s2[ii][1], r[2], r[3]);
            upk2(s2[ii][2], r[4], r[5]);
            upk2(s2[ii][3], r[6], r[7]);
            if (diag) {
                #pragma unroll
                for (int jj = 0; jj < 8; jj++)
                    if (j0 + jj > i0 + ii) r[jj] = -1e30f;
            }
            float mx = r[0];
            #pragma unroll
            for (int jj = 1; jj < 8; jj++) mx = fmaxf(mx, r[jj]);
            #pragma unroll
            for (int off = 8; off > 0; off >>= 1)
                mx = fmaxf(mx, __shfl_xor_sync(0xffffffffu, mx, off));
            float mnew = fmaxf(m_i[ii], mx);
            float corr = ex2f(m_i[ii] - mnew);
            m_i[ii] = mnew;
            float rs = 0.0f;
            #pragma unroll
            for (int jj = 0; jj < 8; jj++) {
                r[jj] = ex2f(r[jj] - mnew);
                rs += r[jj];
            }
            #pragma unroll
            for (int off = 8; off > 0; off >>= 1)
                rs += __shfl_xor_sync(0xffffffffu, rs, off);
            l_i[ii] = l_i[ii] * corr + rs;
            if (tj == 0) Corr[i0 + ii] = corr;
            *(float4*)(Ps + (i0 + ii) * 128 + j0)     = make_float4(r[0], r[1], r[2], r[3]);
            *(float4*)(Ps + (i0 + ii) * 128 + j0 + 4) = make_float4(r[4], r[5], r[6], r[7]);
        }
        __syncthreads();

        // ---- rescale output accumulators by corr (AV row mapping)
        #pragma unroll
        for (int ii = 0; ii < 8; ii++) {
            float c = Corr[ai0 + ii];
            u64 c2 = pk2(c, c);
            mul2(o2[ii][0], c2);
            mul2(o2[ii][1], c2);
            mul2(o2[ii][2], c2);
            mul2(o2[ii][3], c2);
        }

        // ---- AV over this group's j-half
        const int cch = ad0 >> 2;  // logical chunk of d0 (and +1)
        #pragma unroll 2
        for (int jc = 0; jc < 16; jc++) {
            int j = jbase + jc * 4;
            float4 p4[8];
            #pragma unroll
            for (int ii = 0; ii < 8; ii++)
                p4[ii] = *(const float4*)(Ps + (ai0 + ii) * 128 + j);
            u64 v2[4][4];
            #pragma unroll
            for (int rr = 0; rr < 4; rr++) {
                int jr = j + rr;
                int js = jr >> 2;
                float4 va = *(const float4*)(Vt + jr * 64 + (((cch + js) & 15) * 4));
                float4 vb = *(const float4*)(Vt + jr * 64 + (((cch + 1 + js) & 15) * 4));
                v2[rr][0] = pk2(va.x, va.y); v2[rr][1] = pk2(va.z, va.w);
                v2[rr][2] = pk2(vb.x, vb.y); v2[rr][3] = pk2(vb.z, vb.w);
            }
            #pragma unroll
            for (int ii = 0; ii < 8; ii++) {
                float pa[4] = {p4[ii].x, p4[ii].y, p4[ii].z, p4[ii].w};
                #pragma unroll
                for (int rr = 0; rr < 4; rr++) {
                    u64 a2 = pk2(pa[rr], pa[rr]);
                    fma2(o2[ii][0], a2, v2[rr][0]);
                    fma2(o2[ii][1], a2, v2[rr][1]);
                    fma2(o2[ii][2], a2, v2[rr][2]);
                    fma2(o2[ii][3], a2, v2[rr][3]);
                }
            }
        }
    }

    // ---- combine the two j-half partials, normalize, write out
    if (tj == 0) {
        #pragma unroll
        for (int ii = 0; ii < 8; ii++) Lrow[i0 + ii] = l_i[ii];
    }
    if (grp == 1) {
        u64* buf = (u64*)Ks;  // Ks no longer needed
        #pragma unroll
        for (int ii = 0; ii < 8; ii++)
            #pragma unroll
            for (int dc = 0; dc < 4; dc++)
                buf[gt * 32 + ii * 4 + dc] = o2[ii][dc];
    }
    __syncthreads();
    if (grp == 0) {
        u64* buf = (u64*)Ks;
        #pragma unroll
        for (int ii = 0; ii < 8; ii++)
            #pragma unroll
            for (int dc = 0; dc < 4; dc++)
                add2(o2[ii][dc], buf[gt * 32 + ii * 4 + dc]);

        float o[8][8], invl[8];
        #pragma unroll
        for (int ii = 0; ii < 8; ii++) {
            invl[ii] = 1.0f / Lrow[ai0 + ii];
            upk2(o2[ii][0], o[ii][0], o[ii][1]);
            upk2(o2[ii][1], o[ii][2], o[ii][3]);
            upk2(o2[ii][2], o[ii][4], o[ii][5]);
            upk2(o2[ii][3], o[ii][6], o[ii][7]);
        }
        #pragma unroll
        for (int dd = 0; dd < 8; dd++) {
            float* op = Oh + (size_t)(ad0 + dd) * SQ + s0 + ai0;
            float4 w0 = make_float4(o[0][dd] * invl[0], o[1][dd] * invl[1],
                                    o[2][dd] * invl[2], o[3][dd] * invl[3]);
            float4 w1 = make_float4(o[4][dd] * invl[4], o[5][dd] * invl[5],
                                    o[6][dd] * invl[6], o[7][dd] * invl[7]);
            *(float4*)op       = w0;
            *(float4*)(op + 4) = w1;
        }
    }
}

// ---------------------------------------------------------------------------
extern "C" void kernel_launch(void* const* d_in, const int* in_sizes, int n_in,
                              void* d_out, int out_size)
{
    const float* query = (const float*)d_in[0];
    const float* key   = (const float*)d_in[1];
    const float* Wq    = (const float*)d_in[2];
    const float* bq    = (const float*)d_in[3];
    const float* Wk    = (const float*)d_in[4];
    const float* bk    = (const float*)d_in[5];
    const float* Wv    = (const float*)d_in[6];
    const float* bv    = (const float*)d_in[7];

    dim3 g1(SQ / 128, EE / 128, BB * 3);
    proj_kernel<<<g1, 256>>>(query, key, Wq, bq, Wk, bk, Wv, bv);

    const int attn_smem = (64*128 + 64*128 + 128*64 + 128*128) * 4;  // 160KB
    cudaFuncSetAttribute(attn_kernel,
                         cudaFuncAttributeMaxDynamicSharedMemorySize, attn_smem);
    dim3 g2(8, HH, BB);
    attn_kernel<<<g2, 256, attn_smem>>>((float*)d_out);
}

// round 3
// speedup vs baseline: 2.8349x; 2.8349x over previous
#include <cuda_runtime.h>
#include <cstdint>

#define SQ 1024   // sequence length
#define CC 256    // QDIM == KDIM
#define EE 512    // EMBED
#define BB 8      // batch
#define HH 8      // heads
#define DD 64     // head dim

__device__ float g_Q[BB * EE * SQ];
__device__ float g_K[BB * EE * SQ];
__device__ float g_V[BB * EE * SQ];

__device__ __forceinline__ unsigned tf32c(float x) {
    unsigned r; asm("cvt.rna.tf32.f32 %0,%1;" : "=r"(r) : "f"(x)); return r;
}
__device__ __forceinline__ float tf32f(float x) {
    return __uint_as_float(tf32c(x));
}
__device__ __forceinline__ float ex2f(float x) {
    float r; asm("ex2.approx.ftz.f32 %0,%1;" : "=f"(r) : "f"(x)); return r;
}
__device__ __forceinline__ void mma_tf32(
    float& c0, float& c1, float& c2, float& c3,
    unsigned a0, unsigned a1, unsigned a2, unsigned a3,
    unsigned b0, unsigned b1)
{
    asm volatile(
        "mma.sync.aligned.m16n8k8.row.col.f32.tf32.tf32.f32 "
        "{%0,%1,%2,%3},{%4,%5,%6,%7},{%8,%9},{%0,%1,%2,%3};"
        : "+f"(c0), "+f"(c1), "+f"(c2), "+f"(c3)
        : "r"(a0), "r"(a1), "r"(a2), "r"(a3), "r"(b0), "r"(b1));
}

// ---------------------------------------------------------------------------
// Projection: Y[e][s] = W[e][c] X[c][s] + bias[e]   (tf32 mma)
// CTA 128x128, BK=32. 8 warps as 2(m)x4(n), warp tile 64x32 (mt=4, nt=4).
// ---------------------------------------------------------------------------
__global__ __launch_bounds__(256) void proj_kernel(
    const float* __restrict__ q_in, const float* __restrict__ k_in,
    const float* __restrict__ wq, const float* __restrict__ biasq,
    const float* __restrict__ wk, const float* __restrict__ biask,
    const float* __restrict__ wv, const float* __restrict__ biasv)
{
    const int z = blockIdx.z;
    const int b = z / 3;
    const int p = z % 3;
    const float* X    = (p == 0 ? q_in : k_in) + (size_t)b * CC * SQ;
    const float* W    = (p == 0) ? wq : (p == 1 ? wk : wv);
    const float* bias = (p == 0) ? biasq : (p == 1 ? biask : biasv);
    float* Y = (p == 0 ? g_Q : (p == 1 ? g_K : g_V)) + (size_t)b * EE * SQ;

    const int m0 = blockIdx.y * 128;
    const int n0 = blockIdx.x * 128;

    __shared__ __align__(16) float Ws[128 * 36];   // [m][k], pad 36
    __shared__ __align__(16) float Xs[32 * 136];   // [k][n], pad 136

    const int tid  = threadIdx.x;
    const int lane = tid & 31;
    const int wid  = tid >> 5;
    const int mw   = (wid & 1) * 64;
    const int nw   = (wid >> 1) * 32;
    const int r    = lane >> 2;      // 0..7
    const int l    = lane & 3;       // 0..3

    float c[4][4][4];
    #pragma unroll
    for (int mt = 0; mt < 4; mt++)
        #pragma unroll
        for (int nt = 0; nt < 4; nt++)
            #pragma unroll
            for (int e = 0; e < 4; e++) c[mt][nt][e] = 0.0f;

    for (int k0 = 0; k0 < CC; k0 += 32) {
        #pragma unroll
        for (int idx = tid; idx < 1024; idx += 256) {
            int row = idx >> 3, k4 = (idx & 7) * 4;
            float4 w4 = *(const float4*)(W + (size_t)(m0 + row) * CC + k0 + k4);
            float* ps = Ws + row * 36 + k4;
            ps[0] = tf32f(w4.x); ps[1] = tf32f(w4.y);
            ps[2] = tf32f(w4.z); ps[3] = tf32f(w4.w);
        }
        #pragma unroll
        for (int idx = tid; idx < 1024; idx += 256) {
            int k = idx >> 5, n4 = (idx & 31) * 4;
            float4 x4 = *(const float4*)(X + (size_t)(k0 + k) * SQ + n0 + n4);
            float* ps = Xs + k * 136 + n4;
            ps[0] = tf32f(x4.x); ps[1] = tf32f(x4.y);
            ps[2] = tf32f(x4.z); ps[3] = tf32f(x4.w);
        }
        __syncthreads();

        #pragma unroll
        for (int ks = 0; ks < 4; ks++) {
            unsigned a[4][4];
            #pragma unroll
            for (int mt = 0; mt < 4; mt++) {
                const float* ap = Ws + (mw + mt * 16 + r) * 36 + ks * 8 + l;
                a[mt][0] = __float_as_uint(ap[0]);
                a[mt][1] = __float_as_uint(ap[8 * 36]);
                a[mt][2] = __float_as_uint(ap[4]);
                a[mt][3] = __float_as_uint(ap[8 * 36 + 4]);
            }
            #pragma unroll
            for (int nt = 0; nt < 4; nt++) {
                const float* bp = Xs + (ks * 8 + l) * 136 + nw + nt * 8 + r;
                unsigned b0 = __float_as_uint(bp[0]);
                unsigned b1 = __float_as_uint(bp[4 * 136]);
                #pragma unroll
                for (int mt = 0; mt < 4; mt++)
                    mma_tf32(c[mt][nt][0], c[mt][nt][1], c[mt][nt][2], c[mt][nt][3],
                             a[mt][0], a[mt][1], a[mt][2], a[mt][3], b0, b1);
            }
        }
        __syncthreads();
    }

    #pragma unroll
    for (int mt = 0; mt < 4; mt++) {
        int e0 = m0 + mw + mt * 16 + r;
        float bv0 = __ldg(bias + e0);
        float bv1 = __ldg(bias + e0 + 8);
        #pragma unroll
        for (int nt = 0; nt < 4; nt++) {
            int s = n0 + nw + nt * 8 + 2 * l;
            *(float2*)(Y + (size_t)e0 * SQ + s) =
                make_float2(c[mt][nt][0] + bv0, c[mt][nt][1] + bv0);
            *(float2*)(Y + (size_t)(e0 + 8) * SQ + s) =
                make_float2(c[mt][nt][2] + bv1, c[mt][nt][3] + bv1);
        }
    }
}

// ---------------------------------------------------------------------------
// Causal flash attention with tf32 mma. Br=Bc=128, 8 warps x 16 query rows.
// All tiles natural [d][s] layout; pads: Q/K 136, V/P 132 (conflict-free frags).
// ---------------------------------------------------------------------------
#define QKP 136
#define VPP 132

__global__ __launch_bounds__(256, 1) void attn_kernel(float* __restrict__ out)
{
    extern __shared__ float smf[];
    float* Qs = smf;                    // [64][136]  Q^T tf32: [d][i]
    float* Ks = Qs + 64 * QKP;          // [64][136]  [d][j]
    float* Vs = Ks + 64 * QKP;          // [64][132]  [d][j]
    float* Ps = Vs + 64 * VPP;          // [128][132] [i][j]
    float* Os = Ps;                     // reuse as [128][68]

    const int qb = blockIdx.x;
    const int h  = blockIdx.y;
    const int b  = blockIdx.z;

    const float* Qh = g_Q + ((size_t)b * EE + h * DD) * SQ;
    const float* Kh = g_K + ((size_t)b * EE + h * DD) * SQ;
    const float* Vh = g_V + ((size_t)b * EE + h * DD) * SQ;
    float*       Oh = out + ((size_t)b * EE + h * DD) * SQ;

    const int s0   = qb * 128;
    const int tid  = threadIdx.x;
    const int lane = tid & 31;
    const int wid  = tid >> 5;
    const int r    = lane >> 2;
    const int l    = lane & 3;
    const int ib   = wid * 16;          // warp's query-row base

    const float qscale = 0.125f * 1.4426950408889634f;  // 1/sqrt(64)*log2(e)

    for (int t = tid; t < 64 * 32; t += 256) {
        int d = t >> 5, i4 = (t & 31) * 4;
        float4 q = *(const float4*)(Qh + (size_t)d * SQ + s0 + i4);
        float* ps = Qs + d * QKP + i4;
        ps[0] = tf32f(q.x * qscale); ps[1] = tf32f(q.y * qscale);
        ps[2] = tf32f(q.z * qscale); ps[3] = tf32f(q.w * qscale);
    }

    float o[8][4];
    #pragma unroll
    for (int nt = 0; nt < 8; nt++)
        #pragma unroll
        for (int e = 0; e < 4; e++) o[nt][e] = 0.0f;
    float m0r = -1e30f, m1r = -1e30f, l0r = 0.0f, l1r = 0.0f;

    for (int kb = 0; kb <= qb; kb++) {
        __syncthreads();
        const int c0 = kb * 128;
        for (int t = tid; t < 64 * 32; t += 256) {
            int d = t >> 5, j4 = (t & 31) * 4;
            float4 k4 = *(const float4*)(Kh + (size_t)d * SQ + c0 + j4);
            float* pk = Ks + d * QKP + j4;
            pk[0] = tf32f(k4.x); pk[1] = tf32f(k4.y);
            pk[2] = tf32f(k4.z); pk[3] = tf32f(k4.w);
            float4 v4 = *(const float4*)(Vh + (size_t)d * SQ + c0 + j4);
            float* pv = Vs + d * VPP + j4;
            pv[0] = tf32f(v4.x); pv[1] = tf32f(v4.y);
            pv[2] = tf32f(v4.z); pv[3] = tf32f(v4.w);
        }
        __syncthreads();

        // ---- QK^T: scores [16 rows][128 cols] per warp
        float sc[16][4];
        #pragma unroll
        for (int nt = 0; nt < 16; nt++)
            #pragma unroll
            for (int e = 0; e < 4; e++) sc[nt][e] = 0.0f;

        #pragma unroll
        for (int ks = 0; ks < 8; ks++) {
            const float* ap = Qs + (ks * 8 + l) * QKP + ib + r;
            unsigned a0 = __float_as_uint(ap[0]);
            unsigned a1 = __float_as_uint(ap[8]);
            unsigned a2 = __float_as_uint(ap[4 * QKP]);
            unsigned a3 = __float_as_uint(ap[4 * QKP + 8]);
            #pragma unroll
            for (int nt = 0; nt < 16; nt++) {
                const float* bp = Ks + (ks * 8 + l) * QKP + nt * 8 + r;
                unsigned b0 = __float_as_uint(bp[0]);
                unsigned b1 = __float_as_uint(bp[4 * QKP]);
                mma_tf32(sc[nt][0], sc[nt][1], sc[nt][2], sc[nt][3],
                         a0, a1, a2, a3, b0, b1);
            }
        }

        // ---- causal mask on the diagonal block
        if (kb == qb) {
            const int il0 = ib + r, il1 = ib + r + 8;
            #pragma unroll
            for (int nt = 0; nt < 16; nt++) {
                int j = nt * 8 + 2 * l;
                if (j     > il0) sc[nt][0] = -1e30f;
                if (j + 1 > il0) sc[nt][1] = -1e30f;
                if (j     > il1) sc[nt][2] = -1e30f;
                if (j + 1 > il1) sc[nt][3] = -1e30f;
            }
        }

        // ---- online softmax (rows live in a quad: shfl xor 1,2)
        float mx0 = -1e30f, mx1 = -1e30f;
        #pragma unroll
        for (int nt = 0; nt < 16; nt++) {
            mx0 = fmaxf(mx0, fmaxf(sc[nt][0], sc[nt][1]));
            mx1 = fmaxf(mx1, fmaxf(sc[nt][2], sc[nt][3]));
        }
        mx0 = fmaxf(mx0, __shfl_xor_sync(0xffffffffu, mx0, 1));
        mx0 = fmaxf(mx0, __shfl_xor_sync(0xffffffffu, mx0, 2));
        mx1 = fmaxf(mx1, __shfl_xor_sync(0xffffffffu, mx1, 1));
        mx1 = fmaxf(mx1, __shfl_xor_sync(0xffffffffu, mx1, 2));
        float mn0 = fmaxf(m0r, mx0), mn1 = fmaxf(m1r, mx1);
        float corr0 = ex2f(m0r - mn0), corr1 = ex2f(m1r - mn1);
        m0r = mn0; m1r = mn1;

        float rs0 = 0.0f, rs1 = 0.0f;
        #pragma unroll
        for (int nt = 0; nt < 16; nt++) {
            sc[nt][0] = ex2f(sc[nt][0] - mn0); rs0 += sc[nt][0];
            sc[nt][1] = ex2f(sc[nt][1] - mn0); rs0 += sc[nt][1];
            sc[nt][2] = ex2f(sc[nt][2] - mn1); rs1 += sc[nt][2];
            sc[nt][3] = ex2f(sc[nt][3] - mn1); rs1 += sc[nt][3];
        }
        rs0 += __shfl_xor_sync(0xffffffffu, rs0, 1);
        rs0 += __shfl_xor_sync(0xffffffffu, rs0, 2);
        rs1 += __shfl_xor_sync(0xffffffffu, rs1, 1);
        rs1 += __shfl_xor_sync(0xffffffffu, rs1, 2);
        l0r = l0r * corr0 + rs0;
        l1r = l1r * corr1 + rs1;

        // ---- P -> smem (tf32), warp-local rows only
        #pragma unroll
        for (int nt = 0; nt < 16; nt++) {
            int jo = nt * 8 + 2 * l;
            *(float2*)(Ps + (ib + r) * VPP + jo) =
                make_float2(tf32f(sc[nt][0]), tf32f(sc[nt][1]));
            *(float2*)(Ps + (ib + r + 8) * VPP + jo) =
                make_float2(tf32f(sc[nt][2]), tf32f(sc[nt][3]));
        }
        __syncwarp();

        // ---- rescale O accumulators
        #pragma unroll
        for (int nt = 0; nt < 8; nt++) {
            o[nt][0] *= corr0; o[nt][1] *= corr0;
            o[nt][2] *= corr1; o[nt][3] *= corr1;
        }

        // ---- PV: O[16 rows][64 d] per warp
        #pragma unroll
        for (int ks = 0; ks < 16; ks++) {
            const float* ap = Ps + (ib + r) * VPP + ks * 8 + l;
            unsigned a0 = __float_as_uint(ap[0]);
            unsigned a1 = __float_as_uint(ap[8 * VPP]);
            unsigned a2 = __float_as_uint(ap[4]);
            unsigned a3 = __float_as_uint(ap[8 * VPP + 4]);
            #pragma unroll
            for (int nt = 0; nt < 8; nt++) {
                const float* bp = Vs + (nt * 8 + r) * VPP + ks * 8 + l;
                unsigned b0 = __float_as_uint(bp[0]);
                unsigned b1 = __float_as_uint(bp[4]);
                mma_tf32(o[nt][0], o[nt][1], o[nt][2], o[nt][3],
                         a0, a1, a2, a3, b0, b1);
            }
        }
    }

    // ---- epilogue: normalize, stage O as [i][d] (pad 68), coalesced STG
    float inv0 = 1.0f / l0r, inv1 = 1.0f / l1r;
    __syncthreads();
    #pragma unroll
    for (int nt = 0; nt < 8; nt++) {
        int d = nt * 8 + 2 * l;
        float* p0 = Os + (ib + r) * 68 + d;
        float* p1 = Os + (ib + r + 8) * 68 + d;
        p0[0] = o[nt][0] * inv0; p0[1] = o[nt][1] * inv0;
        p1[0] = o[nt][2] * inv1; p1[1] = o[nt][3] * inv1;
    }
    __syncthreads();

    const int dcol = tid & 63;
    const int iblk = tid >> 6;
    #pragma unroll
    for (int g = 0; g < 8; g++) {
        int i4 = iblk * 32 + g * 4;
        float4 w;
        w.x = Os[(i4 + 0) * 68 + dcol];
        w.y = Os[(i4 + 1) * 68 + dcol];
        w.z = Os[(i4 + 2) * 68 + dcol];
        w.w = Os[(i4 + 3) * 68 + dcol];
        *(float4*)(Oh + (size_t)dcol * SQ + s0 + i4) = w;
    }
}

// ---------------------------------------------------------------------------
extern "C" void kernel_launch(void* const* d_in, const int* in_sizes, int n_in,
                              void* d_out, int out_size)
{
    const float* query = (const float*)d_in[0];
    const float* key   = (const float*)d_in[1];
    const float* Wq    = (const float*)d_in[2];
    const float* bq    = (const float*)d_in[3];
    const float* Wk    = (const float*)d_in[4];
    const float* bk    = (const float*)d_in[5];
    const float* Wv    = (const float*)d_in[6];
    const float* bv    = (const float*)d_in[7];

    dim3 g1(SQ / 128, EE / 128, BB * 3);
    proj_kernel<<<g1, 256>>>(query, key, Wq, bq, Wk, bk, Wv, bv);

    const int attn_smem = (64 * QKP * 2 + 64 * VPP + 128 * VPP) * 4;  // 171008
    cudaFuncSetAttribute(attn_kernel,
                         cudaFuncAttributeMaxDynamicSharedMemorySize, attn_smem);
    dim3 g2(SQ / 128, HH, BB);
    attn_kernel<<<g2, 256, attn_smem>>>((float*)d_out);
}